// round 3
// baseline (speedup 1.0000x reference)
#include <cuda_runtime.h>
#include <cuda_bf16.h>
#include <cstdint>

// GroupConv2d: x[16,1024,56,56] f32, w[1024,2,3,3] f32, groups=512, VALID -> out[16,1024,54,54] f32
// One CTA per (batch, group). Group input (2ch x 56x56 = 25KB) staged in SMEM via cp.async.
// Each thread computes a 4-wide x 3-tall output tile for BOTH out-channels (24 outputs),
// so 5 shared input rows serve 3 output rows (row reuse cuts LDS traffic ~45%).

constexpr int HIN = 56, WIN = 56;
constexpr int HOUT = 54, WOUT = 54;
constexpr int IPG = 2, OPG = 2, KS = 3;
constexpr int GROUPS = 512;
constexpr int NBATCH = 16;
constexpr int TPB = 256;
constexpr int IN_PLANE = HIN * WIN;              // 3136
constexpr int IN_ELEMS = IPG * IN_PLANE;         // 6272
constexpr int NCHUNK = 14;                        // 54 cols / 4-wide
constexpr int NROWT = 18;                         // 54 rows / 3-tall
constexpr int NITEMS = NROWT * NCHUNK;            // 252 (< TPB: one item per thread)
constexpr int NW = OPG * IPG * KS * KS;           // 36 weights per group

__device__ __forceinline__ void cp_async16(uint32_t smem_addr, const void* gptr) {
    asm volatile("cp.async.cg.shared.global [%0], [%1], 16;\n"
                 :: "r"(smem_addr), "l"(gptr));
}

__global__ __launch_bounds__(TPB, 4) void gconv_kernel(
    const float* __restrict__ x,
    const float* __restrict__ w,
    float* __restrict__ out)
{
    const int bid = blockIdx.x;
    const int g = bid % GROUPS;
    const int n = bid / GROUPS;

    // +8 pad: edge chunk (ow0=52) reads 2 floats past the last staged row harmlessly.
    __shared__ float s_in[IN_ELEMS + 8];
    __shared__ float s_w[NW];

    // ---- stage input: 6272 contiguous floats = 1568 x 16B cp.async, fully coalesced ----
    {
        const float4* src = reinterpret_cast<const float4*>(
            x + ((size_t)n * (GROUPS * IPG) + (size_t)g * IPG) * IN_PLANE);
        uint32_t sbase = (uint32_t)__cvta_generic_to_shared(s_in);
        #pragma unroll
        for (int i = threadIdx.x; i < IN_ELEMS / 4; i += TPB)
            cp_async16(sbase + i * 16, src + i);
        asm volatile("cp.async.commit_group;\n");
    }
    if (threadIdx.x < NW)
        s_w[threadIdx.x] = w[(size_t)g * NW + threadIdx.x];
    asm volatile("cp.async.wait_group 0;\n");
    __syncthreads();

    const int tid = threadIdx.x;
    if (tid >= NITEMS) return;

    const int rt = tid / NCHUNK;          // row-tile index: output rows r0..r0+2
    const int c  = tid - rt * NCHUNK;     // 4-wide column chunk
    const int r0 = rt * 3;
    const int ow0 = c * 4;

    float acc[OPG][3][4];
    #pragma unroll
    for (int o = 0; o < OPG; o++)
        #pragma unroll
        for (int i = 0; i < 3; i++)
            #pragma unroll
            for (int j = 0; j < 4; j++) acc[o][i][j] = 0.0f;

    // ic loop NOT unrolled: only 18 live weight regs at a time -> fits 64-reg budget.
    #pragma unroll 1
    for (int ic = 0; ic < IPG; ic++) {
        // weights for this in-channel, both out-channels (broadcast LDS, conflict-free)
        float wk[OPG][KS][KS];
        #pragma unroll
        for (int o = 0; o < OPG; o++)
            #pragma unroll
            for (int kh = 0; kh < KS; kh++)
                #pragma unroll
                for (int kw = 0; kw < KS; kw++)
                    wk[o][kh][kw] = s_w[o * (IPG * KS * KS) + ic * (KS * KS) + kh * KS + kw];

        const float* plane = &s_in[ic * IN_PLANE];

        // 5 input rows serve 3 output rows: input row r0+i feeds output row r0+i-kh
        #pragma unroll
        for (int i = 0; i < 5; i++) {
            const float* row = plane + (r0 + i) * WIN + ow0;
            const float4 v0 = *reinterpret_cast<const float4*>(row);      // LDS.128 (16B aligned)
            const float2 v1 = *reinterpret_cast<const float2*>(row + 4);  // LDS.64
            const float in6[6] = {v0.x, v0.y, v0.z, v0.w, v1.x, v1.y};

            #pragma unroll
            for (int kh = 0; kh < KS; kh++) {
                const int ro = i - kh;                 // local output row
                if (ro < 0 || ro > 2) continue;        // compile-time pruned
                #pragma unroll
                for (int o = 0; o < OPG; o++) {
                    #pragma unroll
                    for (int j = 0; j < 4; j++) {
                        acc[o][ro][j] = fmaf(wk[o][kh][0], in6[j],
                                        fmaf(wk[o][kh][1], in6[j + 1],
                                        fmaf(wk[o][kh][2], in6[j + 2], acc[o][ro][j])));
                    }
                }
            }
        }
    }

    // ---- store: rows r0..r0+2, both oc; row base 216B*r -> 8B aligned, float2 stores ----
    float* outp = out + ((size_t)n * (GROUPS * OPG) + (size_t)g * OPG) * (HOUT * WOUT);
    #pragma unroll
    for (int o = 0; o < OPG; o++) {
        #pragma unroll
        for (int i = 0; i < 3; i++) {
            float* op = outp + o * (HOUT * WOUT) + (r0 + i) * WOUT + ow0;
            reinterpret_cast<float2*>(op)[0] = make_float2(acc[o][i][0], acc[o][i][1]);
            if (ow0 + 4 <= WOUT)
                reinterpret_cast<float2*>(op)[1] = make_float2(acc[o][i][2], acc[o][i][3]);
        }
    }
}

extern "C" void kernel_launch(void* const* d_in, const int* in_sizes, int n_in,
                              void* d_out, int out_size)
{
    const float* x = (const float*)d_in[0];
    const float* w = (const float*)d_in[1];
    float* out = (float*)d_out;

    gconv_kernel<<<NBATCH * GROUPS, TPB>>>(x, w, out);
}